// round 1
// baseline (speedup 1.0000x reference)
#include <cuda_runtime.h>
#include <float.h>
#include <math.h>

// Problem shape (fixed by the dataset): B=4096, M=8192, K=32 neighbors.
#define BMAX 4096
#define TPB  256
#define SEG  16          // BMAX / TPB
#define KNB  32

__device__ float g_centrality[BMAX];
__device__ float g_rowloss[BMAX];

// ---------------------------------------------------------------------------
// Kernel 1: centrality[row] = mean(memory_bank[row, :])
// ---------------------------------------------------------------------------
__global__ __launch_bounds__(TPB) void centrality_kernel(
    const float* __restrict__ mem, int B, int M)
{
    int row = blockIdx.x;
    const float4* p = (const float4*)(mem + (size_t)row * M);
    int n4 = M >> 2;
    float s = 0.f;
    for (int j = threadIdx.x; j < n4; j += TPB) {
        float4 v = p[j];
        s += (v.x + v.y) + (v.z + v.w);
    }
    __shared__ float ws[TPB / 32];
    #pragma unroll
    for (int o = 16; o > 0; o >>= 1) s += __shfl_down_sync(0xffffffffu, s, o);
    if ((threadIdx.x & 31) == 0) ws[threadIdx.x >> 5] = s;
    __syncthreads();
    if (threadIdx.x < 32) {
        float t = (threadIdx.x < TPB / 32) ? ws[threadIdx.x] : 0.f;
        #pragma unroll
        for (int o = 4; o > 0; o >>= 1) t += __shfl_down_sync(0xffffffffu, t, o);
        if (threadIdx.x == 0) g_centrality[row] = t / (float)M;
    }
}

// ---------------------------------------------------------------------------
// Kernel 2: per-row loss. One CTA (256 threads) per row.
// ---------------------------------------------------------------------------
__device__ __forceinline__ unsigned long long packf(float v, int idx) {
    unsigned u = __float_as_uint(v);
    u = (u & 0x80000000u) ? ~u : (u | 0x80000000u);   // orderable float bits
    return ((unsigned long long)u << 32) | (unsigned)idx;
}

__global__ __launch_bounds__(TPB) void rowloss_kernel(
    const float* __restrict__ sim, const float* __restrict__ temp_p, int B)
{
    __shared__ float              srow[BMAX];
    __shared__ unsigned long long segkey[TPB];
    __shared__ unsigned long long warpmaxs[TPB / 32];
    __shared__ unsigned int       bitmap[BMAX / 32];
    __shared__ float              topval[KNB];
    __shared__ int                topidx[KNB];
    __shared__ unsigned long long winkey;
    __shared__ float              sh_diag;
    __shared__ float rmn[TPB / 32], rmx[TPB / 32], rcmn[TPB / 32], rcmx[TPB / 32];
    __shared__ float sh_sc[4];    // mn_s, mx_s, mn_c, mx_c

    const int i   = blockIdx.x;
    const int tid = threadIdx.x;
    const float NEG = -FLT_MAX;

    // ---- load row into smem ----
    const float4* rp = (const float4*)(sim + (size_t)i * B);
    for (int j = tid; j < (B >> 2); j += TPB) ((float4*)srow)[j] = rp[j];
    for (int j = tid; j < (B >> 5); j += TPB) bitmap[j] = 0u;
    __syncthreads();
    if (tid == 0) {
        sh_diag = srow[i];
        srow[i] = NEG;                       // exclude diagonal from top-k
        bitmap[i >> 5] |= 1u << (i & 31);
    }
    __syncthreads();

    // ---- initial per-thread segment max (16 contiguous elements each) ----
    {
        int base = tid * SEG;
        unsigned long long best = 0ull;
        #pragma unroll
        for (int j = 0; j < SEG; j++) {
            unsigned long long kk = packf(srow[base + j], base + j);
            if (kk > best) best = kk;
        }
        segkey[tid] = best;
    }
    __syncthreads();

    // ---- 32 rounds of block-argmax tournament ----
    for (int k = 0; k < KNB; k++) {
        unsigned long long v = segkey[tid];
        #pragma unroll
        for (int o = 16; o > 0; o >>= 1) {
            unsigned long long w = __shfl_down_sync(0xffffffffu, v, o);
            if (w > v) v = w;
        }
        if ((tid & 31) == 0) warpmaxs[tid >> 5] = v;
        __syncthreads();
        if (tid < 32) {
            unsigned long long t = (tid < TPB / 32) ? warpmaxs[tid] : 0ull;
            #pragma unroll
            for (int o = 4; o > 0; o >>= 1) {
                unsigned long long w = __shfl_down_sync(0xffffffffu, t, o);
                if (w > t) t = w;
            }
            if (tid == 0) winkey = t;
        }
        __syncthreads();
        int widx = (int)(winkey & 0xffffffffu);
        if (tid == (widx >> 4)) {            // SEG == 16
            topval[k] = srow[widx];
            topidx[k] = widx;
            srow[widx] = NEG;
            bitmap[widx >> 5] |= 1u << (widx & 31);
            int base = tid * SEG;
            unsigned long long best = 0ull;
            #pragma unroll
            for (int j = 0; j < SEG; j++) {
                unsigned long long kk = packf(srow[base + j], base + j);
                if (kk > best) best = kk;
            }
            segkey[tid] = best;
        }
        __syncthreads();
    }

    // ---- min/max of sim row over non-excluded (sentinel-skip) and of
    //      centrality over non-excluded (bitmap-skip) ----
    float mn = FLT_MAX, mx = -FLT_MAX, cmn = FLT_MAX, cmx = -FLT_MAX;
    {
        int base = tid * SEG;
        #pragma unroll
        for (int j = 0; j < SEG; j++) {
            int idx = base + j;
            float v = srow[idx];
            if (v != NEG) { mn = fminf(mn, v); mx = fmaxf(mx, v); }
            if (!((bitmap[idx >> 5] >> (idx & 31)) & 1u)) {
                float c = g_centrality[idx];
                cmn = fminf(cmn, c); cmx = fmaxf(cmx, c);
            }
        }
    }
    #pragma unroll
    for (int o = 16; o > 0; o >>= 1) {
        mn  = fminf(mn,  __shfl_xor_sync(0xffffffffu, mn,  o));
        mx  = fmaxf(mx,  __shfl_xor_sync(0xffffffffu, mx,  o));
        cmn = fminf(cmn, __shfl_xor_sync(0xffffffffu, cmn, o));
        cmx = fmaxf(cmx, __shfl_xor_sync(0xffffffffu, cmx, o));
    }
    if ((tid & 31) == 0) {
        rmn[tid >> 5] = mn; rmx[tid >> 5] = mx;
        rcmn[tid >> 5] = cmn; rcmx[tid >> 5] = cmx;
    }
    __syncthreads();
    if (tid < 32) {
        float a = (tid < TPB / 32) ? rmn[tid]  :  FLT_MAX;
        float b = (tid < TPB / 32) ? rmx[tid]  : -FLT_MAX;
        float c = (tid < TPB / 32) ? rcmn[tid] :  FLT_MAX;
        float d = (tid < TPB / 32) ? rcmx[tid] : -FLT_MAX;
        #pragma unroll
        for (int o = 4; o > 0; o >>= 1) {
            a = fminf(a, __shfl_xor_sync(0xffffffffu, a, o));
            b = fmaxf(b, __shfl_xor_sync(0xffffffffu, b, o));
            c = fminf(c, __shfl_xor_sync(0xffffffffu, c, o));
            d = fmaxf(d, __shfl_xor_sync(0xffffffffu, d, o));
        }
        if (tid == 0) { sh_sc[0] = a; sh_sc[1] = b; sh_sc[2] = c; sh_sc[3] = d; }
    }
    __syncthreads();

    // ---- epilogue: warp 0, one lane per neighbor ----
    if (tid < 32) {
        float mn_s = sh_sc[0], mx_s = sh_sc[1], mn_c = sh_sc[2], mx_c = sh_sc[3];
        float tv = topval[tid];
        int   ti = topidx[tid];
        float dg = sh_diag;

        // logsumexp over extended set (32 neighbors + diagonal)
        float m = tv;
        #pragma unroll
        for (int o = 16; o > 0; o >>= 1) m = fmaxf(m, __shfl_xor_sync(0xffffffffu, m, o));
        m = fmaxf(m, dg);
        float s = expf(tv - m);
        #pragma unroll
        for (int o = 16; o > 0; o >>= 1) s += __shfl_xor_sync(0xffffffffu, s, o);
        s += expf(dg - m);
        float lse = logf(s) + m;

        // positive weights: softmax over 32 neighbors of (norm_sim - norm_cent)*T
        float T  = *temp_p;
        float ns = (tv - mn_s) / (mx_s - mn_s);
        float nc = (g_centrality[ti] - mn_c) / (mx_c - mn_c);
        float a  = (ns - nc) * T;
        float am = a;
        #pragma unroll
        for (int o = 16; o > 0; o >>= 1) am = fmaxf(am, __shfl_xor_sync(0xffffffffu, am, o));
        float pe = expf(a - am);
        float ps = pe;
        #pragma unroll
        for (int o = 16; o > 0; o >>= 1) ps += __shfl_xor_sync(0xffffffffu, ps, o);
        float pw = pe / ps;

        float num = pw * (tv - lse);
        float pwsum = pw;
        #pragma unroll
        for (int o = 16; o > 0; o >>= 1) {
            num   += __shfl_xor_sync(0xffffffffu, num,   o);
            pwsum += __shfl_xor_sync(0xffffffffu, pwsum, o);
        }
        if (tid == 0) {
            float numer = num + (dg - lse);
            float denom = pwsum + 1.0f;
            g_rowloss[i] = -numer / denom;
        }
    }
}

// ---------------------------------------------------------------------------
// Kernel 3: deterministic mean over rows
// ---------------------------------------------------------------------------
__global__ __launch_bounds__(TPB) void reduce_kernel(float* __restrict__ out, int B)
{
    double s = 0.0;
    for (int j = threadIdx.x; j < B; j += TPB) s += (double)g_rowloss[j];
    __shared__ double ws[TPB / 32];
    #pragma unroll
    for (int o = 16; o > 0; o >>= 1) s += __shfl_down_sync(0xffffffffu, s, o);
    if ((threadIdx.x & 31) == 0) ws[threadIdx.x >> 5] = s;
    __syncthreads();
    if (threadIdx.x < 32) {
        double t = (threadIdx.x < TPB / 32) ? ws[threadIdx.x] : 0.0;
        #pragma unroll
        for (int o = 4; o > 0; o >>= 1) t += __shfl_down_sync(0xffffffffu, t, o);
        if (threadIdx.x == 0) out[0] = (float)(t / (double)B);
    }
}

// ---------------------------------------------------------------------------
extern "C" void kernel_launch(void* const* d_in, const int* in_sizes, int n_in,
                              void* d_out, int out_size)
{
    const float* sim = (const float*)d_in[0];
    const float* mem = (const float*)d_in[1];
    // Inputs follow setup_inputs() order: sim, memory_bank, num_neighbors,
    // temperature. Temperature is the LAST input either way.
    const float* temp = (const float*)d_in[n_in - 1];

    int nsim = in_sizes[0];
    int B = 1;
    while ((long long)B * B < (long long)nsim) B <<= 1;   // B = 4096
    int M = in_sizes[1] / B;                               // M = 8192

    centrality_kernel<<<B, TPB>>>(mem, B, M);
    rowloss_kernel<<<B, TPB>>>(sim, temp, B);
    reduce_kernel<<<1, TPB>>>((float*)d_out, B);
}